// round 13
// baseline (speedup 1.0000x reference)
#include <cuda_runtime.h>
#include <stdint.h>

// xxh32 primes
#define P2 2246822519u
#define P3 3266489917u
#define P4 668265263u
#define P5 374761393u

__device__ __forceinline__ uint32_t rotl32(uint32_t v, int r) {
    return (v << r) | (v >> (32 - r));
}

__device__ __forceinline__ uint32_t xxh32_4(uint32_t val, uint32_t seed) {
    uint32_t acc = seed + P5 + 4u;
    acc = acc + val * P3;
    acc = rotl32(acc, 17) * P4;
    acc ^= acc >> 15;
    acc *= P2;
    acc ^= acc >> 13;
    acc *= P3;
    acc ^= acc >> 16;
    return acc;
}

// 256-bit gather load with L2 evict_last (protect the emb table's hot slice).
__device__ __forceinline__ void ldg_el_32B(const void* p,
                                           uint64_t& a, uint64_t& b,
                                           uint64_t& c, uint64_t& d) {
    asm volatile("ld.global.nc.L2::evict_last.v4.b64 {%0,%1,%2,%3}, [%4];"
                 : "=l"(a), "=l"(b), "=l"(c), "=l"(d)
                 : "l"(p));
}

// 256-bit store with L2 evict_last (keep output lines L2-resident so graph
// replays overwrite them in place where possible).
__device__ __forceinline__ void stg_el_32B(void* p,
                                           uint64_t a, uint64_t b,
                                           uint64_t c, uint64_t d) {
    asm volatile("st.global.L2::evict_last.v4.b64 [%0], {%1,%2,%3,%4};"
                 :: "l"(p), "l"(a), "l"(b), "l"(c), "l"(d)
                 : "memory");
}

#define PAIRS_PER_WARP 16

// One-shot warp-centric kernel — best-measured configuration (22.85us kernel)
// across 8 structural variants; the workload is at its DRAM mixed-traffic
// wall (~103MB/iter @ ~4.5TB/s drain):
//  - each lane hashes one pair (lane%16, dup across half-warps)
//  - 4 independent 32B gathers per lane; round k covers pairs 4k..4k+3
//    (4 rows x 256B = 1KB fully-coalesced per round), evict_last in L2
//  - 4 x 32B coalesced evict_last stores per lane
__global__ void unified_embedding_kernel(
    const int* __restrict__ x,        // [N]
    const int* __restrict__ fnum,     // [F]
    const char* __restrict__ emb,     // [levels, 256 bytes]
    char* __restrict__ out,           // [N*F, 256 bytes]
    int N, int F, uint32_t levels)
{
    uint32_t warp_id = (blockIdx.x * blockDim.x + threadIdx.x) >> 5;
    uint32_t lane    = threadIdx.x & 31u;
    uint32_t lane16  = lane & 15u;
    uint32_t sub     = lane >> 3;          // 0..3: row within round
    uint32_t chunk   = lane & 7u;          // 0..7: 32B chunk within row

    uint32_t total = (uint32_t)N * (uint32_t)F;
    uint32_t pair0 = warp_id * PAIRS_PER_WARP;
    if (pair0 >= total) return;

    // Each lane hashes one pair (duplicated across the two half-warps)
    uint32_t my_pair = pair0 + lane16;
    uint32_t i = my_pair / (uint32_t)F;
    uint32_t j = my_pair - i * (uint32_t)F;
    uint32_t val  = (uint32_t)__ldg(&x[i]);
    uint32_t seed = (uint32_t)__ldg(&fnum[j]);
    uint32_t my_idx = xxh32_4(val, seed) % levels;

    // 4 independent 32B gathers per lane; round k covers pairs pair0+4k..+3
    uint64_t va[4], vb[4], vc[4], vd[4];
    #pragma unroll
    for (int k = 0; k < 4; k++) {
        uint32_t src_lane = 4u * k + sub;    // within width-16 group
        uint32_t idx = __shfl_sync(0xffffffffu, my_idx, src_lane, 16);
        const char* src = emb + (size_t)idx * 256 + chunk * 32;
        ldg_el_32B(src, va[k], vb[k], vc[k], vd[k]);
    }

    // Coalesced evict_last stores: round k writes 1KB contiguous per warp
    #pragma unroll
    for (int k = 0; k < 4; k++) {
        uint32_t pair = pair0 + 4u * k + sub;
        char* dst = out + (size_t)pair * 256 + chunk * 32;
        stg_el_32B(dst, va[k], vb[k], vc[k], vd[k]);
    }
}

extern "C" void kernel_launch(void* const* d_in, const int* in_sizes, int n_in,
                              void* d_out, int out_size) {
    const int*  x    = (const int*)d_in[0];
    const int*  fnum = (const int*)d_in[1];
    const char* emb  = (const char*)d_in[2];
    char*       out  = (char*)d_out;

    int N = in_sizes[0];
    int F = in_sizes[1];
    uint32_t levels = (uint32_t)(in_sizes[2] / 64);  // EMB_DIM = 64

    long long total_pairs = (long long)N * F;
    long long warps = (total_pairs + PAIRS_PER_WARP - 1) / PAIRS_PER_WARP;
    int block = 256;
    int warps_per_block = block / 32;
    int grid = (int)((warps + warps_per_block - 1) / warps_per_block);

    unified_embedding_kernel<<<grid, block>>>(x, fnum, emb, out, N, F, levels);
}

// round 14
// speedup vs baseline: 1.0565x; 1.0565x over previous
#include <cuda_runtime.h>
#include <stdint.h>

// xxh32 primes
#define P2 2246822519u
#define P3 3266489917u
#define P4 668265263u
#define P5 374761393u

__device__ __forceinline__ uint32_t rotl32(uint32_t v, int r) {
    return (v << r) | (v >> (32 - r));
}

__device__ __forceinline__ uint32_t xxh32_4(uint32_t val, uint32_t seed) {
    uint32_t acc = seed + P5 + 4u;
    acc = acc + val * P3;
    acc = rotl32(acc, 17) * P4;
    acc ^= acc >> 15;
    acc *= P2;
    acc ^= acc >> 13;
    acc *= P3;
    acc ^= acc >> 16;
    return acc;
}

// 256-bit gather load, default L2 priority.
__device__ __forceinline__ void ldg_32B(const void* p,
                                        uint64_t& a, uint64_t& b,
                                        uint64_t& c, uint64_t& d) {
    asm volatile("ld.global.nc.v4.b64 {%0,%1,%2,%3}, [%4];"
                 : "=l"(a), "=l"(b), "=l"(c), "=l"(d)
                 : "l"(p));
}

// 256-bit store with L2 evict_last (keep output lines L2-resident).
__device__ __forceinline__ void stg_el_32B(void* p,
                                           uint64_t a, uint64_t b,
                                           uint64_t c, uint64_t d) {
    asm volatile("st.global.L2::evict_last.v4.b64 [%0], {%1,%2,%3,%4};"
                 :: "l"(p), "l"(a), "l"(b), "l"(c), "l"(d)
                 : "memory");
}

#define PAIRS_PER_WARP 16

// One-shot warp-centric kernel — R9 configuration (best measured e2e,
// 27.7us; kernel time within noise of global best). The workload sits at
// its DRAM mixed-traffic wall (~103MB/iter @ ~4.5TB/s drain); 9 structural
// variants all land 22.85-23.7us kernel time.
//  - each lane hashes one pair (lane%16, dup across half-warps)
//  - 4 independent 32B gathers per lane; round k covers pairs 4k..4k+3
//    (4 rows x 256B = 1KB fully-coalesced per round)
//  - 4 x 32B coalesced evict_last stores per lane
__global__ void unified_embedding_kernel(
    const int* __restrict__ x,        // [N]
    const int* __restrict__ fnum,     // [F]
    const char* __restrict__ emb,     // [levels, 256 bytes]
    char* __restrict__ out,           // [N*F, 256 bytes]
    int N, int F, uint32_t levels)
{
    uint32_t warp_id = (blockIdx.x * blockDim.x + threadIdx.x) >> 5;
    uint32_t lane    = threadIdx.x & 31u;
    uint32_t lane16  = lane & 15u;
    uint32_t sub     = lane >> 3;          // 0..3: row within round
    uint32_t chunk   = lane & 7u;          // 0..7: 32B chunk within row

    uint32_t total = (uint32_t)N * (uint32_t)F;
    uint32_t pair0 = warp_id * PAIRS_PER_WARP;
    if (pair0 >= total) return;

    // Each lane hashes one pair (duplicated across the two half-warps)
    uint32_t my_pair = pair0 + lane16;
    uint32_t i = my_pair / (uint32_t)F;
    uint32_t j = my_pair - i * (uint32_t)F;
    uint32_t val  = (uint32_t)__ldg(&x[i]);
    uint32_t seed = (uint32_t)__ldg(&fnum[j]);
    uint32_t my_idx = xxh32_4(val, seed) % levels;

    // 4 independent 32B gathers per lane; round k covers pairs pair0+4k..+3
    uint64_t va[4], vb[4], vc[4], vd[4];
    #pragma unroll
    for (int k = 0; k < 4; k++) {
        uint32_t src_lane = 4u * k + sub;    // within width-16 group
        uint32_t idx = __shfl_sync(0xffffffffu, my_idx, src_lane, 16);
        const char* src = emb + (size_t)idx * 256 + chunk * 32;
        ldg_32B(src, va[k], vb[k], vc[k], vd[k]);
    }

    // Coalesced evict_last stores: round k writes 1KB contiguous per warp
    #pragma unroll
    for (int k = 0; k < 4; k++) {
        uint32_t pair = pair0 + 4u * k + sub;
        char* dst = out + (size_t)pair * 256 + chunk * 32;
        stg_el_32B(dst, va[k], vb[k], vc[k], vd[k]);
    }
}

extern "C" void kernel_launch(void* const* d_in, const int* in_sizes, int n_in,
                              void* d_out, int out_size) {
    const int*  x    = (const int*)d_in[0];
    const int*  fnum = (const int*)d_in[1];
    const char* emb  = (const char*)d_in[2];
    char*       out  = (char*)d_out;

    int N = in_sizes[0];
    int F = in_sizes[1];
    uint32_t levels = (uint32_t)(in_sizes[2] / 64);  // EMB_DIM = 64

    long long total_pairs = (long long)N * F;
    long long warps = (total_pairs + PAIRS_PER_WARP - 1) / PAIRS_PER_WARP;
    int block = 256;
    int warps_per_block = block / 32;
    int grid = (int)((warps + warps_per_block - 1) / warps_per_block);

    unified_embedding_kernel<<<grid, block>>>(x, fnum, emb, out, N, F, levels);
}

// round 15
// speedup vs baseline: 1.0578x; 1.0012x over previous
#include <cuda_runtime.h>
#include <stdint.h>

// xxh32 primes
#define P2 2246822519u
#define P3 3266489917u
#define P4 668265263u
#define P5 374761393u

__device__ __forceinline__ uint32_t rotl32(uint32_t v, int r) {
    return (v << r) | (v >> (32 - r));
}

__device__ __forceinline__ uint32_t xxh32_4(uint32_t val, uint32_t seed) {
    uint32_t acc = seed + P5 + 4u;
    acc = acc + val * P3;
    acc = rotl32(acc, 17) * P4;
    acc ^= acc >> 15;
    acc *= P2;
    acc ^= acc >> 13;
    acc *= P3;
    acc ^= acc >> 16;
    return acc;
}

// 256-bit gather load, default L2 priority.
__device__ __forceinline__ void ldg_32B(const void* p,
                                        uint64_t& a, uint64_t& b,
                                        uint64_t& c, uint64_t& d) {
    asm volatile("ld.global.nc.v4.b64 {%0,%1,%2,%3}, [%4];"
                 : "=l"(a), "=l"(b), "=l"(c), "=l"(d)
                 : "l"(p));
}

// 256-bit store with L2 evict_last (keep output lines L2-resident).
__device__ __forceinline__ void stg_el_32B(void* p,
                                           uint64_t a, uint64_t b,
                                           uint64_t c, uint64_t d) {
    asm volatile("st.global.L2::evict_last.v4.b64 [%0], {%1,%2,%3,%4};"
                 :: "l"(p), "l"(a), "l"(b), "l"(c), "l"(d)
                 : "memory");
}

#define PAIRS_PER_WARP 16

// FINAL: one-shot warp-centric kernel — best measured configuration
// (27.17us e2e / 23.0us kernel). The workload sits at its DRAM
// mixed-traffic wall (~103MB/iter @ ~4.5TB/s mixed drain); nine structural
// variants all land 22.85-23.7us kernel time and every SM-side lever
// (issue, occupancy, waves, duty cycle, regs, L2 policy) was individually
// tested and falsified.
//  - each lane hashes one pair (lane%16, dup across half-warps)
//  - 4 independent 32B gathers per lane; round k covers pairs 4k..4k+3
//    (4 rows x 256B = 1KB fully-coalesced per round)
//  - 4 x 32B coalesced evict_last stores per lane
__global__ void unified_embedding_kernel(
    const int* __restrict__ x,        // [N]
    const int* __restrict__ fnum,     // [F]
    const char* __restrict__ emb,     // [levels, 256 bytes]
    char* __restrict__ out,           // [N*F, 256 bytes]
    int N, int F, uint32_t levels)
{
    uint32_t warp_id = (blockIdx.x * blockDim.x + threadIdx.x) >> 5;
    uint32_t lane    = threadIdx.x & 31u;
    uint32_t lane16  = lane & 15u;
    uint32_t sub     = lane >> 3;          // 0..3: row within round
    uint32_t chunk   = lane & 7u;          // 0..7: 32B chunk within row

    uint32_t total = (uint32_t)N * (uint32_t)F;
    uint32_t pair0 = warp_id * PAIRS_PER_WARP;
    if (pair0 >= total) return;

    // Each lane hashes one pair (duplicated across the two half-warps)
    uint32_t my_pair = pair0 + lane16;
    uint32_t i = my_pair / (uint32_t)F;
    uint32_t j = my_pair - i * (uint32_t)F;
    uint32_t val  = (uint32_t)__ldg(&x[i]);
    uint32_t seed = (uint32_t)__ldg(&fnum[j]);
    uint32_t my_idx = xxh32_4(val, seed) % levels;

    // 4 independent 32B gathers per lane; round k covers pairs pair0+4k..+3
    uint64_t va[4], vb[4], vc[4], vd[4];
    #pragma unroll
    for (int k = 0; k < 4; k++) {
        uint32_t src_lane = 4u * k + sub;    // within width-16 group
        uint32_t idx = __shfl_sync(0xffffffffu, my_idx, src_lane, 16);
        const char* src = emb + (size_t)idx * 256 + chunk * 32;
        ldg_32B(src, va[k], vb[k], vc[k], vd[k]);
    }

    // Coalesced evict_last stores: round k writes 1KB contiguous per warp
    #pragma unroll
    for (int k = 0; k < 4; k++) {
        uint32_t pair = pair0 + 4u * k + sub;
        char* dst = out + (size_t)pair * 256 + chunk * 32;
        stg_el_32B(dst, va[k], vb[k], vc[k], vd[k]);
    }
}

extern "C" void kernel_launch(void* const* d_in, const int* in_sizes, int n_in,
                              void* d_out, int out_size) {
    const int*  x    = (const int*)d_in[0];
    const int*  fnum = (const int*)d_in[1];
    const char* emb  = (const char*)d_in[2];
    char*       out  = (char*)d_out;

    int N = in_sizes[0];
    int F = in_sizes[1];
    uint32_t levels = (uint32_t)(in_sizes[2] / 64);  // EMB_DIM = 64

    long long total_pairs = (long long)N * F;
    long long warps = (total_pairs + PAIRS_PER_WARP - 1) / PAIRS_PER_WARP;
    int block = 256;
    int warps_per_block = block / 32;
    int grid = (int)((warps + warps_per_block - 1) / warps_per_block);

    unified_embedding_kernel<<<grid, block>>>(x, fnum, emb, out, N, F, levels);
}